// round 1
// baseline (speedup 1.0000x reference)
#include <cuda_runtime.h>
#include <cstddef>

// Problem constants
constexpr int B_ = 8;
constexpr int N_ = 2048;
constexpr int INC = 128;
constexpr int HIDC = 256;
constexpr int OUTC = 32;
constexpr int BN = B_ * N_;

// Scratch (device globals: no allocation allowed)
__device__ float g_deg_inv[BN];
__device__ float g_agg[(size_t)BN * HIDC];  // agg1 (stride INC) then agg2 (stride HIDC)
__device__ float g_h[(size_t)BN * HIDC];    // hidden activations

using ull = unsigned long long;

__device__ __forceinline__ ull pack2(float a, float b) {
    ull r;
    asm("mov.b64 %0, {%1, %2};" : "=l"(r)
        : "r"(__float_as_uint(a)), "r"(__float_as_uint(b)));
    return r;
}
__device__ __forceinline__ ull fma2(ull a, ull b, ull c) {
    ull d;
    asm("fma.rn.f32x2 %0, %1, %2, %3;" : "=l"(d) : "l"(a), "l"(b), "l"(c));
    return d;
}
__device__ __forceinline__ float2 unpack2(ull v) {
    unsigned lo, hi;
    asm("mov.b64 {%0, %1}, %2;" : "=r"(lo), "=r"(hi) : "l"(v));
    return make_float2(__uint_as_float(lo), __uint_as_float(hi));
}

// ---------------------------------------------------------------------------
// Aggregation: agg[b,j,0:C] = deg_inv[b,j] * sum_i (A[b,i,j]!=0) * src[b,i,0:C]
// FIRST=true also computes deg_inv (each (b,j) column handled by exactly one
// block because the block tile spans the full channel dim).
// Block: 256 threads = 16(ty: 4 j each) x 16(tx: C/16 d each, strided by 64).
// ---------------------------------------------------------------------------
template <int C, bool FIRST>
__global__ __launch_bounds__(256)
void agg_kernel(const float* __restrict__ xsrc, const int* __restrict__ A) {
    constexpr int TJ = 64, KI = 32;
    constexpr int NQ = C / 64;  // float4 chunks per thread (2 or 4)

    __shared__ __align__(16) float sM[KI][TJ];
    __shared__ __align__(16) float sX[KI][C];
    __shared__ float sdeg[TJ];

    const int b = blockIdx.y;
    const int j0 = blockIdx.x * TJ;
    const int tid = threadIdx.x;
    const int tx = tid & 15, ty = tid >> 4;

    if (FIRST && tid < TJ) sdeg[tid] = 0.0f;
    __syncthreads();

    ull acc[4][NQ * 2];
#pragma unroll
    for (int jr = 0; jr < 4; ++jr)
#pragma unroll
        for (int p = 0; p < NQ * 2; ++p) acc[jr][p] = 0ull;

    const float* src = FIRST ? xsrc : g_h;
    const float4* src4 = reinterpret_cast<const float4*>(src) + (size_t)b * N_ * (C / 4);
    const int* Ab = A + (size_t)b * N_ * N_ + j0;

    for (int it = 0; it < N_ / KI; ++it) {
        // Load A tile [KI][TJ], convert to {0,1} mask, accumulate degree.
#pragma unroll
        for (int r = 0; r < (KI * TJ) / 256; ++r) {
            int e = tid + r * 256;
            int i = e >> 6, j = e & 63;
            float m = (Ab[(size_t)(it * KI + i) * N_ + j] != 0) ? 1.0f : 0.0f;
            sM[i][j] = m;
            if (FIRST) atomicAdd(&sdeg[j], m);
        }
        // Load source tile [KI][C] as float4 (coalesced).
#pragma unroll
        for (int r = 0; r < (KI * C / 4) / 256; ++r) {
            int e = tid + r * 256;
            int i = e / (C / 4), c4 = e % (C / 4);
            reinterpret_cast<float4*>(sX[i])[c4] =
                src4[(size_t)(it * KI + i) * (C / 4) + c4];
        }
        __syncthreads();

#pragma unroll 8
        for (int ki = 0; ki < KI; ++ki) {
            float4 mj = *reinterpret_cast<const float4*>(&sM[ki][ty * 4]);
            ull m2[4] = {pack2(mj.x, mj.x), pack2(mj.y, mj.y),
                         pack2(mj.z, mj.z), pack2(mj.w, mj.w)};
            ull xv[NQ * 2];
#pragma unroll
            for (int q = 0; q < NQ; ++q) {
                float4 v = *reinterpret_cast<const float4*>(&sX[ki][tx * 4 + q * 64]);
                xv[q * 2]     = pack2(v.x, v.y);
                xv[q * 2 + 1] = pack2(v.z, v.w);
            }
#pragma unroll
            for (int jr = 0; jr < 4; ++jr)
#pragma unroll
                for (int p = 0; p < NQ * 2; ++p)
                    acc[jr][p] = fma2(m2[jr], xv[p], acc[jr][p]);
        }
        __syncthreads();
    }

    float dinv[4];
    if (FIRST) {
#pragma unroll
        for (int jr = 0; jr < 4; ++jr)
            dinv[jr] = 1.0f / fmaxf(sdeg[ty * 4 + jr], 1.0f);
        if (tx == 0) {
#pragma unroll
            for (int jr = 0; jr < 4; ++jr)
                g_deg_inv[b * N_ + j0 + ty * 4 + jr] = dinv[jr];
        }
    } else {
#pragma unroll
        for (int jr = 0; jr < 4; ++jr)
            dinv[jr] = g_deg_inv[b * N_ + j0 + ty * 4 + jr];
    }

#pragma unroll
    for (int jr = 0; jr < 4; ++jr) {
        float* drow = g_agg + ((size_t)b * N_ + j0 + ty * 4 + jr) * C;
#pragma unroll
        for (int q = 0; q < NQ; ++q) {
            float2 lo = unpack2(acc[jr][q * 2]);
            float2 hi = unpack2(acc[jr][q * 2 + 1]);
            float4 o = make_float4(lo.x * dinv[jr], lo.y * dinv[jr],
                                   hi.x * dinv[jr], hi.y * dinv[jr]);
            *reinterpret_cast<float4*>(drow + tx * 4 + q * 64) = o;
        }
    }
}

// ---------------------------------------------------------------------------
// Dense layer 1: h = relu(agg1 @ W1_l + x @ W1_r + b1)
// Treated as one GEMM with combined K=256 (first 128 from agg1/W1_l,
// second 128 from x/W1_r). Tile 64 rows x 128 cols, 256 threads.
// ---------------------------------------------------------------------------
__global__ __launch_bounds__(256)
void dense1_kernel(const float* __restrict__ x,
                   const float* __restrict__ W1l, const float* __restrict__ W1r,
                   const float* __restrict__ b1) {
    constexpr int TM = 64, TN = 128, KT = 16;
    __shared__ __align__(16) float sA[TM][KT + 1];
    __shared__ __align__(16) float sW[KT][TN];

    const int tid = threadIdx.x;
    const int tx = tid & 15, ty = tid >> 4;
    const int r0 = blockIdx.y * TM;
    const int c0 = blockIdx.x * TN;

    ull acc[4][4];
#pragma unroll
    for (int rr = 0; rr < 4; ++rr)
#pragma unroll
        for (int p = 0; p < 4; ++p) acc[rr][p] = 0ull;

#pragma unroll 1
    for (int kt = 0; kt < 16; ++kt) {
        const float* srcA = (kt < 8) ? g_agg : x;
        const float* srcW = (kt < 8) ? W1l : W1r;
        const int kb = (kt & 7) * KT;
        {
            int row = tid >> 2, kq = (tid & 3) * 4;
            float4 v = *reinterpret_cast<const float4*>(
                srcA + (size_t)(r0 + row) * INC + kb + kq);
            sA[row][kq] = v.x; sA[row][kq + 1] = v.y;
            sA[row][kq + 2] = v.z; sA[row][kq + 3] = v.w;
        }
#pragma unroll
        for (int r = 0; r < 2; ++r) {
            int e = tid + r * 256;
            int k = e >> 5, c4 = e & 31;
            reinterpret_cast<float4*>(sW[k])[c4] =
                *reinterpret_cast<const float4*>(
                    srcW + (size_t)(kb + k) * HIDC + c0 + c4 * 4);
        }
        __syncthreads();

#pragma unroll
        for (int k = 0; k < KT; ++k) {
            ull a2[4];
#pragma unroll
            for (int rr = 0; rr < 4; ++rr) {
                float a = sA[ty * 4 + rr][k];
                a2[rr] = pack2(a, a);
            }
            ull wv[4];
#pragma unroll
            for (int q = 0; q < 2; ++q) {
                float4 w = *reinterpret_cast<const float4*>(&sW[k][tx * 4 + q * 64]);
                wv[q * 2]     = pack2(w.x, w.y);
                wv[q * 2 + 1] = pack2(w.z, w.w);
            }
#pragma unroll
            for (int rr = 0; rr < 4; ++rr)
#pragma unroll
                for (int p = 0; p < 4; ++p)
                    acc[rr][p] = fma2(a2[rr], wv[p], acc[rr][p]);
        }
        __syncthreads();
    }

#pragma unroll
    for (int rr = 0; rr < 4; ++rr) {
        float* hrow = g_h + (size_t)(r0 + ty * 4 + rr) * HIDC + c0;
#pragma unroll
        for (int q = 0; q < 2; ++q) {
            float4 bq = *reinterpret_cast<const float4*>(b1 + c0 + tx * 4 + q * 64);
            float2 lo = unpack2(acc[rr][q * 2]);
            float2 hi = unpack2(acc[rr][q * 2 + 1]);
            float4 o = make_float4(fmaxf(lo.x + bq.x, 0.0f), fmaxf(lo.y + bq.y, 0.0f),
                                   fmaxf(hi.x + bq.z, 0.0f), fmaxf(hi.y + bq.w, 0.0f));
            *reinterpret_cast<float4*>(hrow + tx * 4 + q * 64) = o;
        }
    }
}

// ---------------------------------------------------------------------------
// Dense layer 2 + bias + log_softmax, writes both tuple outputs.
// Combined K=512 (agg2/W2_l then h/W2_r). Tile 128 rows x 32 cols.
// ---------------------------------------------------------------------------
__global__ __launch_bounds__(256)
void dense2_kernel(const float* __restrict__ W2l, const float* __restrict__ W2r,
                   const float* __restrict__ b2, float* __restrict__ out,
                   int write_raw) {
    constexpr int TM = 128, KT = 16;
    __shared__ __align__(16) float sA[TM][KT + 1];
    __shared__ __align__(16) float sW[KT][OUTC];
    __shared__ float sOut[TM][OUTC + 1];

    const int tid = threadIdx.x;
    const int tx = tid & 7, ty = tid >> 3;  // tx: 8 col-groups of 4; ty: 32 row-groups of 4
    const int r0 = blockIdx.x * TM;

    ull acc[4][2];
#pragma unroll
    for (int rr = 0; rr < 4; ++rr) { acc[rr][0] = 0ull; acc[rr][1] = 0ull; }

#pragma unroll 1
    for (int kt = 0; kt < 32; ++kt) {
        const float* srcA = (kt < 16) ? g_agg : g_h;
        const float* srcW = (kt < 16) ? W2l : W2r;
        const int kb = (kt & 15) * KT;
#pragma unroll
        for (int r = 0; r < 2; ++r) {
            int e = tid + r * 256;
            int row = e >> 2, kq = (e & 3) * 4;
            float4 v = *reinterpret_cast<const float4*>(
                srcA + (size_t)(r0 + row) * HIDC + kb + kq);
            sA[row][kq] = v.x; sA[row][kq + 1] = v.y;
            sA[row][kq + 2] = v.z; sA[row][kq + 3] = v.w;
        }
        if (tid < 128) {
            int k = tid >> 3, c4 = tid & 7;
            reinterpret_cast<float4*>(sW[k])[c4] =
                *reinterpret_cast<const float4*>(srcW + (size_t)(kb + k) * OUTC + c4 * 4);
        }
        __syncthreads();

#pragma unroll
        for (int k = 0; k < KT; ++k) {
            float4 wq = *reinterpret_cast<const float4*>(&sW[k][tx * 4]);
            ull wv0 = pack2(wq.x, wq.y);
            ull wv1 = pack2(wq.z, wq.w);
#pragma unroll
            for (int rr = 0; rr < 4; ++rr) {
                float a = sA[ty * 4 + rr][k];
                ull a2 = pack2(a, a);
                acc[rr][0] = fma2(a2, wv0, acc[rr][0]);
                acc[rr][1] = fma2(a2, wv1, acc[rr][1]);
            }
        }
        __syncthreads();
    }

    float4 bq = *reinterpret_cast<const float4*>(b2 + tx * 4);
#pragma unroll
    for (int rr = 0; rr < 4; ++rr) {
        float2 lo = unpack2(acc[rr][0]);
        float2 hi = unpack2(acc[rr][1]);
        int row = ty * 4 + rr;
        sOut[row][tx * 4 + 0] = lo.x + bq.x;
        sOut[row][tx * 4 + 1] = lo.y + bq.y;
        sOut[row][tx * 4 + 2] = hi.x + bq.z;
        sOut[row][tx * 4 + 3] = hi.y + bq.w;
    }
    __syncthreads();

    // log_softmax: one warp per row, 32 cols == 32 lanes
    const int lane = tid & 31, wid = tid >> 5;
#pragma unroll 1
    for (int rit = 0; rit < TM / 8; ++rit) {
        int row = rit * 8 + wid;
        float v = sOut[row][lane];
        float m = v;
#pragma unroll
        for (int o = 16; o > 0; o >>= 1)
            m = fmaxf(m, __shfl_xor_sync(0xffffffffu, m, o));
        float s = expf(v - m);
#pragma unroll
        for (int o = 16; o > 0; o >>= 1)
            s += __shfl_xor_sync(0xffffffffu, s, o);
        float lsm = v - m - logf(s);
        size_t gi = (size_t)(r0 + row) * OUTC + lane;
        out[gi] = lsm;
        if (write_raw) out[(size_t)BN * OUTC + gi] = v;
    }
}

// ---------------------------------------------------------------------------
extern "C" void kernel_launch(void* const* d_in, const int* in_sizes, int n_in,
                              void* d_out, int out_size) {
    const float* x   = (const float*)d_in[0];
    const int*   A   = (const int*)d_in[1];
    const float* W1l = (const float*)d_in[2];
    const float* W1r = (const float*)d_in[3];
    const float* b1  = (const float*)d_in[4];
    const float* W2l = (const float*)d_in[5];
    const float* W2r = (const float*)d_in[6];
    const float* b2  = (const float*)d_in[7];
    float* out = (float*)d_out;
    (void)in_sizes; (void)n_in;

    const int write_raw = (out_size >= 2 * BN * OUTC) ? 1 : 0;

    // agg1 (+degree), dense1, agg2, dense2+log_softmax — stream-ordered.
    agg_kernel<INC, true><<<dim3(N_ / 64, B_), 256>>>(x, A);
    dense1_kernel<<<dim3(HIDC / 128, BN / 64), 256>>>(x, W1l, W1r, b1);
    agg_kernel<HIDC, false><<<dim3(N_ / 64, B_), 256>>>(nullptr, A);
    dense2_kernel<<<BN / 128, 256>>>(W2l, W2r, b2, out, write_raw);
}

// round 3
// speedup vs baseline: 2.8690x; 2.8690x over previous
#include <cuda_runtime.h>
#include <cuda_bf16.h>
#include <cstdint>
#include <cstddef>

// Problem constants
constexpr int B_ = 8;
constexpr int N_ = 2048;
constexpr int INC = 128;
constexpr int HIDC = 256;
constexpr int OUTC = 32;
constexpr int BN = B_ * N_;

// Scratch (device globals: no allocation allowed)
__device__ __align__(16) float g_deg[BN];
__device__ __align__(16) float g_agg[(size_t)BN * HIDC];
__device__ __align__(16) float g_h[(size_t)BN * HIDC];
__device__ __align__(16) __nv_bfloat16 g_T_hi[(size_t)B_ * HIDC * N_];  // [b][d][i]
__device__ __align__(16) __nv_bfloat16 g_T_lo[(size_t)B_ * HIDC * N_];
__device__ __align__(16) __nv_bfloat16 g_Mt[(size_t)B_ * N_ * N_];      // [b][j][i] mask^T

using ull = unsigned long long;

#define SWZ(off) ((off) ^ (((off) >> 3) & 0x70))

__device__ __forceinline__ uint32_t smem_u32(const void* p) {
    uint32_t a;
    asm("{ .reg .u64 t; cvta.to.shared.u64 t, %1; cvt.u32.u64 %0, t; }"
        : "=r"(a) : "l"(p));
    return a;
}
__device__ __forceinline__ void cpa16(uint32_t dst, const void* src) {
    asm volatile("cp.async.cg.shared.global [%0], [%1], 16;" :: "r"(dst), "l"(src));
}
__device__ __forceinline__ void ldsm4(uint32_t* r, uint32_t addr) {
    asm volatile("ldmatrix.sync.aligned.m8n8.x4.shared.b16 {%0,%1,%2,%3}, [%4];"
                 : "=r"(r[0]), "=r"(r[1]), "=r"(r[2]), "=r"(r[3]) : "r"(addr));
}
__device__ __forceinline__ void mma_bf16(float* c, const uint32_t* a,
                                         uint32_t b0, uint32_t b1) {
    asm volatile(
        "mma.sync.aligned.m16n8k16.row.col.f32.bf16.bf16.f32 "
        "{%0,%1,%2,%3}, {%4,%5,%6,%7}, {%8,%9}, {%0,%1,%2,%3};"
        : "+f"(c[0]), "+f"(c[1]), "+f"(c[2]), "+f"(c[3])
        : "r"(a[0]), "r"(a[1]), "r"(a[2]), "r"(a[3]), "r"(b0), "r"(b1));
}

// packed fp32 fma helpers for SIMT dense layers
__device__ __forceinline__ ull pack2(float a, float b) {
    ull r;
    asm("mov.b64 %0, {%1, %2};" : "=l"(r)
        : "r"(__float_as_uint(a)), "r"(__float_as_uint(b)));
    return r;
}
__device__ __forceinline__ ull fma2(ull a, ull b, ull c) {
    ull d;
    asm("fma.rn.f32x2 %0, %1, %2, %3;" : "=l"(d) : "l"(a), "l"(b), "l"(c));
    return d;
}
__device__ __forceinline__ float2 unpack2(ull v) {
    unsigned lo, hi;
    asm("mov.b64 {%0, %1}, %2;" : "=r"(lo), "=r"(hi) : "l"(v));
    return make_float2(__uint_as_float(lo), __uint_as_float(hi));
}

// ---------------------------------------------------------------------------
__global__ __launch_bounds__(256) void zero_deg_kernel() {
    g_deg[blockIdx.x * 256 + threadIdx.x] = 0.0f;
}

// ---------------------------------------------------------------------------
// A int32 [b][i][j] -> Mt bf16 [b][j][i]; fused degree (sum over i per j).
// Block handles a 64i x 64j tile.
// ---------------------------------------------------------------------------
__global__ __launch_bounds__(256)
void mask_convert_kernel(const int* __restrict__ A) {
    __shared__ __nv_bfloat16 sT[64][72];
    __shared__ float sdeg[64];
    const int t = threadIdx.x;
    const int j0 = blockIdx.x * 64, i0 = blockIdx.y * 64, b = blockIdx.z;
    if (t < 64) sdeg[t] = 0.0f;
    __syncthreads();

    const int4* Ap = reinterpret_cast<const int4*>(
        A + (size_t)b * N_ * N_ + (size_t)i0 * N_ + j0);
    const int j4 = t & 15;        // int4 index within j-row (4 j's)
    const int rbase = t >> 4;     // 0..15
    float s0 = 0, s1 = 0, s2 = 0, s3 = 0;
#pragma unroll
    for (int p = 0; p < 4; ++p) {
        int il = rbase + p * 16;
        int4 v = Ap[(size_t)il * (N_ / 4) + j4];
        float m0 = v.x ? 1.0f : 0.0f, m1 = v.y ? 1.0f : 0.0f;
        float m2 = v.z ? 1.0f : 0.0f, m3 = v.w ? 1.0f : 0.0f;
        s0 += m0; s1 += m1; s2 += m2; s3 += m3;
        sT[j4 * 4 + 0][il] = __float2bfloat16(m0);
        sT[j4 * 4 + 1][il] = __float2bfloat16(m1);
        sT[j4 * 4 + 2][il] = __float2bfloat16(m2);
        sT[j4 * 4 + 3][il] = __float2bfloat16(m3);
    }
    atomicAdd(&sdeg[j4 * 4 + 0], s0);
    atomicAdd(&sdeg[j4 * 4 + 1], s1);
    atomicAdd(&sdeg[j4 * 4 + 2], s2);
    atomicAdd(&sdeg[j4 * 4 + 3], s3);
    __syncthreads();
    if (t < 64) atomicAdd(&g_deg[b * N_ + j0 + t], sdeg[t]);

#pragma unroll
    for (int p = 0; p < 2; ++p) {
        int idx = t + p * 256;
        int jr = idx >> 3, c = idx & 7;
        uint4 v = *reinterpret_cast<const uint4*>(&sT[jr][c * 8]);
        *reinterpret_cast<uint4*>(
            g_Mt + ((size_t)(b * N_ + j0 + jr)) * N_ + i0 + c * 8) = v;
    }
}

// ---------------------------------------------------------------------------
// Transpose + bf16 hi/lo split: src [b][i][C] fp32 -> g_T_hi/lo [b][d][i] bf16
// ---------------------------------------------------------------------------
template <int C, bool FROM_H>
__global__ __launch_bounds__(256)
void convertT_kernel(const float* __restrict__ xin) {
    __shared__ float sT[64][65];
    const int t = threadIdx.x;
    const int b = blockIdx.z, i0 = blockIdx.x * 64, d0 = blockIdx.y * 64;
    const float* src = FROM_H ? g_h : xin;

#pragma unroll
    for (int p = 0; p < 4; ++p) {
        int e = t + p * 256;
        int row = e >> 4, c4 = e & 15;
        float4 v = *reinterpret_cast<const float4*>(
            src + ((size_t)(b * N_ + i0 + row)) * C + d0 + c4 * 4);
        sT[row][c4 * 4 + 0] = v.x; sT[row][c4 * 4 + 1] = v.y;
        sT[row][c4 * 4 + 2] = v.z; sT[row][c4 * 4 + 3] = v.w;
    }
    __syncthreads();

    const int d = t >> 2, ic = (t & 3) * 16;
    uint32_t hb[8], lb[8];
#pragma unroll
    for (int q = 0; q < 8; ++q) {
        float v0 = sT[ic + q * 2][d], v1 = sT[ic + q * 2 + 1][d];
        __nv_bfloat16 h0 = __float2bfloat16(v0);
        __nv_bfloat16 h1 = __float2bfloat16(v1);
        __nv_bfloat16 l0 = __float2bfloat16(v0 - __bfloat162float(h0));
        __nv_bfloat16 l1 = __float2bfloat16(v1 - __bfloat162float(h1));
        __nv_bfloat162 hp; hp.x = h0; hp.y = h1;
        __nv_bfloat162 lp; lp.x = l0; lp.y = l1;
        hb[q] = *reinterpret_cast<uint32_t*>(&hp);
        lb[q] = *reinterpret_cast<uint32_t*>(&lp);
    }
    size_t obase = ((size_t)(b * C + d0 + d)) * N_ + i0 + ic;
    reinterpret_cast<uint4*>(g_T_hi + obase)[0] = make_uint4(hb[0], hb[1], hb[2], hb[3]);
    reinterpret_cast<uint4*>(g_T_hi + obase)[1] = make_uint4(hb[4], hb[5], hb[6], hb[7]);
    reinterpret_cast<uint4*>(g_T_lo + obase)[0] = make_uint4(lb[0], lb[1], lb[2], lb[3]);
    reinterpret_cast<uint4*>(g_T_lo + obase)[1] = make_uint4(lb[4], lb[5], lb[6], lb[7]);
}

// ---------------------------------------------------------------------------
// HMMA aggregation: agg[b,j,d] = (1/max(deg,1)) * sum_i Mt[b,j,i]*XT[b,d,i]
// CTA = 64 j x 128 d; 8 warps (2j x 4d); warp = 32j x 32d; K-step 64.
// cp.async double-buffered SW128 smem; ldmatrix fragments; bf16 hi/lo split.
// ---------------------------------------------------------------------------
template <int C>
__global__ __launch_bounds__(256)
void agg_mma_kernel() {
    extern __shared__ __align__(1024) char smem[];
    constexpr int NIT = N_ / 64;
    constexpr uint32_t MOFF = 0, XOFF = 16384;

    const int tid = threadIdx.x, lane = tid & 31, wid = tid >> 5;
    const int b = blockIdx.z, j0 = blockIdx.x * 64, d0 = blockIdx.y * 128;
    const int jw = wid & 1, dw = wid >> 1;
    const uint32_t sb = smem_u32(smem);

    float acc[2][4][4];
#pragma unroll
    for (int mg = 0; mg < 2; ++mg)
#pragma unroll
        for (int ng = 0; ng < 4; ++ng)
#pragma unroll
            for (int q = 0; q < 4; ++q) acc[mg][ng][q] = 0.0f;

    const __nv_bfloat16* Mb = g_Mt + ((size_t)(b * N_ + j0)) * N_;

    auto load_stage = [&](int stage, int it) {
        const int i0 = it * 64;
#pragma unroll
        for (int p = 0; p < 2; ++p) {
            int idx = tid + p * 256;
            int row = idx >> 3, c = idx & 7;
            const void* src = Mb + (size_t)row * N_ + i0 + c * 8;
            uint32_t dst = sb + MOFF + stage * 8192 +
                           SWZ((uint32_t)(row * 128 + c * 16));
            cpa16(dst, src);
        }
#pragma unroll
        for (int p = 0; p < 8; ++p) {
            int idx = tid + p * 256;
            int r = idx >> 3, c = idx & 7;
            int hl = r >> 7, d = d0 + (r & 127);
            const __nv_bfloat16* g = hl ? g_T_lo : g_T_hi;
            const void* src = g + ((size_t)(b * C + d)) * N_ + i0 + c * 8;
            uint32_t dst = sb + XOFF + stage * 32768 + hl * 16384 +
                           SWZ((uint32_t)((r & 127) * 128 + c * 16));
            cpa16(dst, src);
        }
        asm volatile("cp.async.commit_group;");
    };

    load_stage(0, 0);

#pragma unroll 1
    for (int it = 0; it < NIT; ++it) {
        const int cur = it & 1;
        if (it + 1 < NIT) {
            load_stage(cur ^ 1, it + 1);
            asm volatile("cp.async.wait_group 1;");
        } else {
            asm volatile("cp.async.wait_group 0;");
        }
        __syncthreads();

        const uint32_t mbase = sb + MOFF + cur * 8192;
        const uint32_t xbase = sb + XOFF + cur * 32768;
#pragma unroll
        for (int kk = 0; kk < 4; ++kk) {
            uint32_t a[2][4];
#pragma unroll
            for (int mg = 0; mg < 2; ++mg) {
                uint32_t addr = mbase + SWZ((uint32_t)(
                    (jw * 32 + mg * 16 + (lane & 15)) * 128 +
                    kk * 32 + (lane >> 4) * 16));
                ldsm4(a[mg], addr);
            }
#pragma unroll
            for (int hl = 0; hl < 2; ++hl) {
                uint32_t bf[2][4];
#pragma unroll
                for (int ng = 0; ng < 2; ++ng) {
                    int rowB = dw * 32 + ng * 16 + (lane & 7) + ((lane >> 4) << 3);
                    uint32_t addr = xbase + hl * 16384 + SWZ((uint32_t)(
                        rowB * 128 + kk * 32 + ((lane >> 3) & 1) * 16));
                    ldsm4(bf[ng], addr);
                }
#pragma unroll
                for (int mg = 0; mg < 2; ++mg)
#pragma unroll
                    for (int ng = 0; ng < 2; ++ng)
#pragma unroll
                        for (int sub = 0; sub < 2; ++sub)
                            mma_bf16(acc[mg][ng * 2 + sub], a[mg],
                                     bf[ng][sub * 2], bf[ng][sub * 2 + 1]);
            }
        }
        __syncthreads();
    }

    // epilogue: scale by 1/max(deg,1), store fp32
    const int rbase = j0 + jw * 32 + (lane >> 2);
    float dv[2][2];
#pragma unroll
    for (int mg = 0; mg < 2; ++mg)
#pragma unroll
        for (int h = 0; h < 2; ++h)
            dv[mg][h] = 1.0f / fmaxf(g_deg[b * N_ + rbase + mg * 16 + h * 8], 1.0f);

#pragma unroll
    for (int mg = 0; mg < 2; ++mg) {
#pragma unroll
        for (int ng = 0; ng < 4; ++ng) {
            int d = d0 + dw * 32 + ng * 8 + (lane & 3) * 2;
            int jl = j0 + jw * 32 + mg * 16 + (lane >> 2);
            float2 v0 = make_float2(acc[mg][ng][0] * dv[mg][0],
                                    acc[mg][ng][1] * dv[mg][0]);
            float2 v1 = make_float2(acc[mg][ng][2] * dv[mg][1],
                                    acc[mg][ng][3] * dv[mg][1]);
            *reinterpret_cast<float2*>(g_agg + ((size_t)(b * N_ + jl)) * C + d) = v0;
            *reinterpret_cast<float2*>(g_agg + ((size_t)(b * N_ + jl + 8)) * C + d) = v1;
        }
    }
}

// ---------------------------------------------------------------------------
// Dense layer 1: h = relu(agg1 @ W1_l + x @ W1_r + b1)  (SIMT fp32x2)
// ---------------------------------------------------------------------------
__global__ __launch_bounds__(256)
void dense1_kernel(const float* __restrict__ x,
                   const float* __restrict__ W1l, const float* __restrict__ W1r,
                   const float* __restrict__ b1) {
    constexpr int TM = 64, TN = 128, KT = 16;
    __shared__ __align__(16) float sA[TM][KT + 1];
    __shared__ __align__(16) float sW[KT][TN];

    const int tid = threadIdx.x;
    const int tx = tid & 15, ty = tid >> 4;
    const int r0 = blockIdx.y * TM;
    const int c0 = blockIdx.x * TN;

    ull acc[4][4];
#pragma unroll
    for (int rr = 0; rr < 4; ++rr)
#pragma unroll
        for (int p = 0; p < 4; ++p) acc[rr][p] = 0ull;

#pragma unroll 1
    for (int kt = 0; kt < 16; ++kt) {
        const float* srcA = (kt < 8) ? g_agg : x;
        const float* srcW = (kt < 8) ? W1l : W1r;
        const int kb = (kt & 7) * KT;
        {
            int row = tid >> 2, kq = (tid & 3) * 4;
            float4 v = *reinterpret_cast<const float4*>(
                srcA + (size_t)(r0 + row) * INC + kb + kq);
            sA[row][kq] = v.x; sA[row][kq + 1] = v.y;
            sA[row][kq + 2] = v.z; sA[row][kq + 3] = v.w;
        }
#pragma unroll
        for (int r = 0; r < 2; ++r) {
            int e = tid + r * 256;
            int k = e >> 5, c4 = e & 31;
            reinterpret_cast<float4*>(sW[k])[c4] =
                *reinterpret_cast<const float4*>(
                    srcW + (size_t)(kb + k) * HIDC + c0 + c4 * 4);
        }
        __syncthreads();

#pragma unroll
        for (int k = 0; k < KT; ++k) {
            ull a2[4];
#pragma unroll
            for (int rr = 0; rr < 4; ++rr) {
                float a = sA[ty * 4 + rr][k];
                a2[rr] = pack2(a, a);
            }
            ull wv[4];
#pragma unroll
            for (int q = 0; q < 2; ++q) {
                float4 w = *reinterpret_cast<const float4*>(&sW[k][tx * 4 + q * 64]);
                wv[q * 2]     = pack2(w.x, w.y);
                wv[q * 2 + 1] = pack2(w.z, w.w);
            }
#pragma unroll
            for (int rr = 0; rr < 4; ++rr)
#pragma unroll
                for (int p = 0; p < 4; ++p)
                    acc[rr][p] = fma2(a2[rr], wv[p], acc[rr][p]);
        }
        __syncthreads();
    }

#pragma unroll
    for (int rr = 0; rr < 4; ++rr) {
        float* hrow = g_h + (size_t)(r0 + ty * 4 + rr) * HIDC + c0;
#pragma unroll
        for (int q = 0; q < 2; ++q) {
            float4 bq = *reinterpret_cast<const float4*>(b1 + c0 + tx * 4 + q * 64);
            float2 lo = unpack2(acc[rr][q * 2]);
            float2 hi = unpack2(acc[rr][q * 2 + 1]);
            float4 o = make_float4(fmaxf(lo.x + bq.x, 0.0f), fmaxf(lo.y + bq.y, 0.0f),
                                   fmaxf(hi.x + bq.z, 0.0f), fmaxf(hi.y + bq.w, 0.0f));
            *reinterpret_cast<float4*>(hrow + tx * 4 + q * 64) = o;
        }
    }
}

// ---------------------------------------------------------------------------
// Dense layer 2 + bias + log_softmax
// ---------------------------------------------------------------------------
__global__ __launch_bounds__(256)
void dense2_kernel(const float* __restrict__ W2l, const float* __restrict__ W2r,
                   const float* __restrict__ b2, float* __restrict__ out,
                   int write_raw) {
    constexpr int TM = 128, KT = 16;
    __shared__ __align__(16) float sA[TM][KT + 1];
    __shared__ __align__(16) float sW[KT][OUTC];
    __shared__ float sOut[TM][OUTC + 1];

    const int tid = threadIdx.x;
    const int tx = tid & 7, ty = tid >> 3;
    const int r0 = blockIdx.x * TM;

    ull acc[4][2];
#pragma unroll
    for (int rr = 0; rr < 4; ++rr) { acc[rr][0] = 0ull; acc[rr][1] = 0ull; }

#pragma unroll 1
    for (int kt = 0; kt < 32; ++kt) {
        const float* srcA = (kt < 16) ? g_agg : g_h;
        const float* srcW = (kt < 16) ? W2l : W2r;
        const int kb = (kt & 15) * KT;
#pragma unroll
        for (int r = 0; r < 2; ++r) {
            int e = tid + r * 256;
            int row = e >> 2, kq = (e & 3) * 4;
            float4 v = *reinterpret_cast<const float4*>(
                srcA + (size_t)(r0 + row) * HIDC + kb + kq);
            sA[row][kq] = v.x; sA[row][kq + 1] = v.y;
            sA[row][kq + 2] = v.z; sA[row][kq + 3] = v.w;
        }
        if (tid < 128) {
            int k = tid >> 3, c4 = tid & 7;
            reinterpret_cast<float4*>(sW[k])[c4] =
                *reinterpret_cast<const float4*>(srcW + (size_t)(kb + k) * OUTC + c4 * 4);
        }
        __syncthreads();

#pragma unroll
        for (int k = 0; k < KT; ++k) {
            float4 wq = *reinterpret_cast<const float4*>(&sW[k][tx * 4]);
            ull wv0 = pack2(wq.x, wq.y);
            ull wv1 = pack2(wq.z, wq.w);
#pragma unroll
            for (int rr = 0; rr < 4; ++rr) {
                float a = sA[ty * 4 + rr][k];
                ull a2 = pack2(a, a);
                acc[rr][0] = fma2(a2, wv0, acc[rr][0]);
                acc[rr][1] = fma2(a2, wv1, acc[rr][1]);
            }
        }
        __syncthreads();
    }

    float4 bq = *reinterpret_cast<const float4*>(b2 + tx * 4);
#pragma unroll
    for (int rr = 0; rr < 4; ++rr) {
        float2 lo = unpack2(acc[rr][0]);
        float2 hi = unpack2(acc[rr][1]);
        int row = ty * 4 + rr;
        sOut[row][tx * 4 + 0] = lo.x + bq.x;
        sOut[row][tx * 4 + 1] = lo.y + bq.y;
        sOut[row][tx * 4 + 2] = hi.x + bq.z;
        sOut[row][tx * 4 + 3] = hi.y + bq.w;
    }
    __syncthreads();

    const int lane = tid & 31, wid = tid >> 5;
#pragma unroll 1
    for (int rit = 0; rit < TM / 8; ++rit) {
        int row = rit * 8 + wid;
        float v = sOut[row][lane];
        float m = v;
#pragma unroll
        for (int o = 16; o > 0; o >>= 1)
            m = fmaxf(m, __shfl_xor_sync(0xffffffffu, m, o));
        float s = expf(v - m);
#pragma unroll
        for (int o = 16; o > 0; o >>= 1)
            s += __shfl_xor_sync(0xffffffffu, s, o);
        float lsm = v - m - logf(s);
        size_t gi = (size_t)(r0 + row) * OUTC + lane;
        out[gi] = lsm;
        if (write_raw) out[(size_t)BN * OUTC + gi] = v;
    }
}

// ---------------------------------------------------------------------------
extern "C" void kernel_launch(void* const* d_in, const int* in_sizes, int n_in,
                              void* d_out, int out_size) {
    const float* x   = (const float*)d_in[0];
    const int*   A   = (const int*)d_in[1];
    const float* W1l = (const float*)d_in[2];
    const float* W1r = (const float*)d_in[3];
    const float* b1  = (const float*)d_in[4];
    const float* W2l = (const float*)d_in[5];
    const float* W2r = (const float*)d_in[6];
    const float* b2  = (const float*)d_in[7];
    float* out = (float*)d_out;
    (void)in_sizes; (void)n_in;

    const int write_raw = (out_size >= 2 * BN * OUTC) ? 1 : 0;

    constexpr int AGG_SMEM = 16384 + 2 * 32768;  // 81920 B
    static int configured = 0;
    if (!configured) {
        cudaFuncSetAttribute(agg_mma_kernel<INC>,
                             cudaFuncAttributeMaxDynamicSharedMemorySize, AGG_SMEM);
        cudaFuncSetAttribute(agg_mma_kernel<HIDC>,
                             cudaFuncAttributeMaxDynamicSharedMemorySize, AGG_SMEM);
        configured = 1;
    }

    zero_deg_kernel<<<BN / 256, 256>>>();
    mask_convert_kernel<<<dim3(N_ / 64, N_ / 64, B_), 256>>>(A);
    convertT_kernel<INC, false><<<dim3(N_ / 64, INC / 64, B_), 256>>>(x);
    agg_mma_kernel<INC><<<dim3(N_ / 64, 1, B_), 256, AGG_SMEM>>>();
    dense1_kernel<<<dim3(HIDC / 128, BN / 64), 256>>>(x, W1l, W1r, b1);
    convertT_kernel<HIDC, true><<<dim3(N_ / 64, HIDC / 64, B_), 256>>>(nullptr);
    agg_mma_kernel<HIDC><<<dim3(N_ / 64, HIDC / 128, B_), 256, AGG_SMEM>>>();
    dense2_kernel<<<BN / 128, 256>>>(W2l, W2r, b2, out, write_raw);
}